// round 12
// baseline (speedup 1.0000x reference)
#include <cuda_runtime.h>
#include <cuda_fp16.h>

// 5x5 median filter, reflect padding, [16,3,256,256] fp32.
//
// fp16x2 packed median (2 pixels per half2 lane), stride-2 packing:
// P[r][c] = (half v[c], half v[c+2]) built once in the smem load phase.
// Pair g (pixels 4tx+g, 4tx+g+2) uses packed columns P[.][4tx+g .. 4tx+g+4].
// Shared-4 set selections + per-pair 3-op tournament extensions, then
// forgetful rank-7-of-13.
// Round 12: 512-thread blocks (32x16), tile 128x16 (loader 5.2 slots/thread
// vs 6.4); minmax8 with TWO elided first-layer CAS via slot assignment:
// (w0,w1) = row0 (2ndmax<=max), (w2,w3) = row1 (third<=mx, proven).

#define BX 32
#define BY 16
#define PPT 4
#define OUT_W (BX * PPT)        // 128
#define OUT_H BY                // 16
#define PAD 2
#define TILE_W (OUT_W + 2*PAD)  // 132 source columns
#define TILE_H (OUT_H + 2*PAD)  // 20
#define PROW 132                // packed-row stride in half2 (528B = 33*16B)
#define IMG 256

__device__ __forceinline__ void cas2(__half2& a, __half2& b) {
    __half2 lo = __hmin2(a, b);
    __half2 hi = __hmax2(a, b);
    a = lo;
    b = hi;
}

// Optimal 9-CAS sorting network for 5 elements (packed).
__device__ __forceinline__ void sort5p(__half2& a, __half2& b, __half2& c,
                                       __half2& d, __half2& e) {
    cas2(a, b); cas2(d, e); cas2(c, e); cas2(c, d); cas2(b, e);
    cas2(a, d); cas2(a, c); cas2(b, d); cas2(b, c);
}

// Branch-free reflect for pad<=2 on [0,255]: -2->2, -1->1, 256->254, 257->253.
__device__ __forceinline__ int refl255(int x) {
    return 255 - abs(255 - abs(x));
}

__global__ __launch_bounds__(BX * BY, 3) void median5_kernel(
    const float* __restrict__ in, float* __restrict__ out) {
    // Packed tile: P[r][c] = (half v[c], half v[c+2]); valid c = 0..129.
    __shared__ __half2 P[TILE_H][PROW];

    const int plane = blockIdx.z;  // 48 planes
    const float* src = in + (size_t)plane * IMG * IMG;
    float* dst = out + (size_t)plane * IMG * IMG;

    const int bx = blockIdx.x * OUT_W;
    const int by = blockIdx.y * OUT_H;
    const int tx = threadIdx.x;
    const int ty = threadIdx.y;

    // ---- Slot-structured halo loader ----
    // col-slots: c = tx + 32k, k = 0..4 (k=4 valid iff tx<4  => c<132)
    // row-slots: r = ty + 16j, j = 0..1 (j=1 valid iff ty<4  => r<20)
    {
        int gxs[5];
        bool stx[5], sty[5];  // store predicates: c<=129 (x-half), c>=2 (y-half)
        #pragma unroll
        for (int k = 0; k < 5; k++) {
            int c = tx + 32 * k;
            gxs[k] = refl255(bx + c - PAD);
            stx[k] = (c <= TILE_W - 3);
            sty[k] = (c >= 2);
        }
        int gy0 = refl255(by + ty - PAD);
        int gy1 = refl255(by + ty + 16 - PAD);

        #pragma unroll
        for (int j = 0; j < 2; j++) {
            int r = ty + 16 * j;
            if (j == 1 && ty >= TILE_H - 16) break;  // r<20
            const float* rowsrc = src + (j == 0 ? gy0 : gy1) * IMG;
            __half* base = reinterpret_cast<__half*>(&P[r][0]);
            #pragma unroll
            for (int k = 0; k < 5; k++) {
                int c = tx + 32 * k;
                if (k == 4 && tx >= TILE_W - 4 * 32) break;  // c<132
                __half h = __float2half_rn(rowsrc[gxs[k]]);
                if (stx[k]) base[2 * c] = h;            // x-half of P[r][c]
                if (sty[k]) base[2 * (c - 2) + 1] = h;  // y-half of P[r][c-2]
            }
        }
    }
    __syncthreads();

    // Read 6 packed columns x 5 rows (uint4 + uint2 LDS, 16B aligned).
    __half2 col[6][5];
    #pragma unroll
    for (int r = 0; r < 5; r++) {
        const __half2* rowp = &P[ty + r][tx * PPT];
        uint4 q = *reinterpret_cast<const uint4*>(rowp);
        uint2 q2 = *reinterpret_cast<const uint2*>(rowp + 4);
        col[0][r] = *reinterpret_cast<__half2*>(&q.x);
        col[1][r] = *reinterpret_cast<__half2*>(&q.y);
        col[2][r] = *reinterpret_cast<__half2*>(&q.z);
        col[3][r] = *reinterpret_cast<__half2*>(&q.w);
        col[4][r] = *reinterpret_cast<__half2*>(&q2.x);
        col[5][r] = *reinterpret_cast<__half2*>(&q2.y);
    }
    #pragma unroll
    for (int k = 0; k < 6; k++)
        sort5p(col[k][0], col[k][1], col[k][2], col[k][3], col[k][4]);

    // Candidate sets for the two pairs (pair 0: cols 0..4, pair 1: cols 1..5).
    // Slot layout for minmax8 elision:
    //   w0<=w1 : row0 (2nd max, max)        [proven sorted]
    //   w2<=w3 : row1 (third-of-top3, mx)   [proven sorted: third<=mx]
    //   w4     : row1 max(y,e)
    //   w5,w6  : row2 mids x2,x3 (unordered)
    //   w7     : row2 extension
    __half2 w[2][8], s[2][5];

    // ---- Row 0 (column minima): top-2 set of 5. ----
    {
        __half2 x1 = col[1][0], x2 = col[2][0], x3 = col[3][0], x4 = col[4][0];
        cas2(x1, x2); cas2(x3, x4);
        __half2 T1 = __hmax2(x2, x4);
        __half2 T2 = __hmax2(__hmin2(x2, x4), __hmax2(x1, x3));
        __half2 e0 = col[0][0], e1 = col[5][0];
        w[0][1] = __hmax2(T1, e0); w[0][0] = __hmax2(T2, __hmin2(T1, e0));
        w[1][1] = __hmax2(T1, e1); w[1][0] = __hmax2(T2, __hmin2(T1, e1));
    }
    // ---- Row 1: top-3 set of 5: {mx, max(y,e), max(mn,min(y,e))}. ----
    {
        __half2 x1 = col[1][1], x2 = col[2][1], x3 = col[3][1], x4 = col[4][1];
        cas2(x1, x2); cas2(x3, x4);
        __half2 y  = __hmax2(x1, x3);
        __half2 mx = __hmax2(x2, x4), mn = __hmin2(x2, x4);
        __half2 e0 = col[0][1], e1 = col[5][1];
        w[0][3] = mx; w[0][4] = __hmax2(y, e0); w[0][2] = __hmax2(mn, __hmin2(y, e0));
        w[1][3] = mx; w[1][4] = __hmax2(y, e1); w[1][2] = __hmax2(mn, __hmin2(y, e1));
    }
    // ---- Row 2 (column medians): middle-3 set of 5. ----
    {
        __half2 x1 = col[1][2], x2 = col[2][2], x3 = col[3][2], x4 = col[4][2];
        cas2(x1, x2); cas2(x3, x4); cas2(x1, x3); cas2(x2, x4);
        __half2 e0 = col[0][2], e1 = col[5][2];
        w[0][5] = x2; w[0][6] = x3; w[0][7] = __hmin2(__hmax2(x1, e0), x4);
        w[1][5] = x2; w[1][6] = x3; w[1][7] = __hmin2(__hmax2(x1, e1), x4);
    }
    // ---- Row 3: bottom-3 set of 5. ----
    {
        __half2 x1 = col[1][3], x2 = col[2][3], x3 = col[3][3], x4 = col[4][3];
        cas2(x1, x2); cas2(x3, x4);
        __half2 z = __hmin2(x2, x4);
        __half2 m = __hmin2(x1, x3), M = __hmax2(x1, x3);
        __half2 e0 = col[0][3], e1 = col[5][3];
        s[0][0] = m; s[0][1] = __hmin2(z, e0); s[0][2] = __hmin2(M, __hmax2(z, e0));
        s[1][0] = m; s[1][1] = __hmin2(z, e1); s[1][2] = __hmin2(M, __hmax2(z, e1));
    }
    // ---- Row 4 (column maxima): bottom-2 set of 5. ----
    {
        __half2 x1 = col[1][4], x2 = col[2][4], x3 = col[3][4], x4 = col[4][4];
        cas2(x1, x2); cas2(x3, x4);
        __half2 B1 = __hmin2(x1, x3);
        __half2 B2 = __hmin2(__hmax2(x1, x3), __hmin2(x2, x4));
        __half2 e0 = col[0][4], e1 = col[5][4];
        s[0][3] = __hmin2(B1, e0); s[0][4] = __hmin2(B2, __hmax2(B1, e0));
        s[1][3] = __hmin2(B1, e1); s[1][4] = __hmin2(B2, __hmax2(B1, e1));
    }

    // Forgetful selection: median = rank 7 (1-indexed) of the 13 candidates.
    __half2 res[2];
    #pragma unroll
    for (int g = 0; g < 2; g++) {
        __half2 w0 = w[g][0], w1 = w[g][1], w2 = w[g][2], w3 = w[g][3];
        __half2 w4 = w[g][4], w5 = w[g][5], w6 = w[g][6], w7 = w[g][7];

        // minmax8 (tree); (w0,w1) and (w2,w3) pre-ordered -> 8 CAS.
        cas2(w4, w5); cas2(w6, w7);
        cas2(w0, w2); cas2(w4, w6); cas2(w0, w4);   // w0 = min8
        cas2(w1, w3); cas2(w5, w7); cas2(w3, w7);   // w7 = max8
        w0 = s[g][0];
        // minmax7: survivors w1..w5.
        cas2(w0, w1); cas2(w2, w3); cas2(w4, w5);
        cas2(w0, w2); cas2(w4, w6); cas2(w0, w4);
        cas2(w1, w3); cas2(w5, w6); cas2(w3, w6);
        w0 = s[g][1];
        // minmax6: survivors w1..w4.
        cas2(w0, w1); cas2(w2, w3); cas2(w4, w5);
        cas2(w0, w2); cas2(w0, w4);
        cas2(w1, w3); cas2(w3, w5);
        w0 = s[g][2];
        // minmax5: survivors w1, w2, w4.
        cas2(w0, w1); cas2(w2, w3); cas2(w0, w2); cas2(w1, w3); cas2(w0, w4); cas2(w4, w3);
        w0 = s[g][3];
        // minmax4 on (w0, w1, w2, w4): survivors w1, w2.
        cas2(w0, w1); cas2(w2, w4); cas2(w0, w2); cas2(w1, w4);
        // med3(s4, w1, w2) via 4-op identity.
        __half2 a = s[g][4];
        res[g] = __hmax2(__hmin2(a, w1), __hmin2(__hmax2(a, w1), w2));
    }

    // Unpack: pair0 = pixels (0,2), pair1 = pixels (1,3).
    float2 p0 = __half22float2(res[0]);
    float2 p1 = __half22float2(res[1]);
    float4 r4 = make_float4(p0.x, p1.x, p0.y, p1.y);

    const int gy = by + ty;
    *reinterpret_cast<float4*>(&dst[gy * IMG + bx + tx * PPT]) = r4;
}

extern "C" void kernel_launch(void* const* d_in, const int* in_sizes, int n_in,
                              void* d_out, int out_size) {
    const float* image = (const float*)d_in[0];
    float* out = (float*)d_out;
    (void)in_sizes; (void)n_in; (void)out_size;

    dim3 block(BX, BY);
    dim3 grid(IMG / OUT_W, IMG / OUT_H, 16 * 3);
    median5_kernel<<<grid, block>>>(image, out);
}

// round 13
// speedup vs baseline: 1.0860x; 1.0860x over previous
#include <cuda_runtime.h>
#include <cuda_fp16.h>

// 5x5 median filter, reflect padding, [16,3,256,256] fp32.
//
// fp16x2 packed median, stride-2 packing P[c] = (v[c], v[c+2]).
// Round 13: sort only the 4 packed columns holding each scalar column ONCE
// (C0,C1,C4,C5 = scalars v0..v7), then reconstruct sorted C2=(v2,v4) and
// C3=(v3,v5) lane-wise via PRMT of sorted columns (exact bit-moves).
// Loader stores each scalar exactly once (packed cols ==2,3 mod 4 unused).
// Selections + double-elided forgetful rank-7-of-13 as validated r5-r12.

#define BX 16
#define BY 16
#define PPT 4
#define OUT_W (BX * PPT)        // 64
#define OUT_H BY                // 16
#define PAD 2
#define TILE_W (OUT_W + 2*PAD)  // 68 source columns
#define TILE_H (OUT_H + 2*PAD)  // 20
#define PROW 68                 // packed-row stride in half2 (272B = 17*16B)
#define IMG 256

__device__ __forceinline__ void cas2(__half2& a, __half2& b) {
    __half2 lo = __hmin2(a, b);
    __half2 hi = __hmax2(a, b);
    a = lo;
    b = hi;
}

// Optimal 9-CAS sorting network for 5 elements (packed).
__device__ __forceinline__ void sort5p(__half2& a, __half2& b, __half2& c,
                                       __half2& d, __half2& e) {
    cas2(a, b); cas2(d, e); cas2(c, e); cas2(c, d); cas2(b, e);
    cas2(a, d); cas2(a, c); cas2(b, d); cas2(b, c);
}

// (a.y, b.x) as a half2 — lane-wise column recombination (exact).
__device__ __forceinline__ __half2 midcol(__half2 a, __half2 b) {
    unsigned int r = __byte_perm(*reinterpret_cast<unsigned int*>(&a),
                                 *reinterpret_cast<unsigned int*>(&b), 0x5432);
    return *reinterpret_cast<__half2*>(&r);
}

// Branch-free reflect for pad<=2 on [0,255]: -2->2, -1->1, 256->254, 257->253.
__device__ __forceinline__ int refl255(int x) {
    return 255 - abs(255 - abs(x));
}

__global__ __launch_bounds__(BX * BY, 6) void median5_kernel(
    const float* __restrict__ in, float* __restrict__ out) {
    // Packed tile: P[r][c] = (half v[c], half v[c+2]) for c%4 in {0,1} only.
    __shared__ __half2 P[TILE_H][PROW];

    const int plane = blockIdx.z;  // 48 planes
    const float* src = in + (size_t)plane * IMG * IMG;
    float* dst = out + (size_t)plane * IMG * IMG;

    const int bx = blockIdx.x * OUT_W;
    const int by = blockIdx.y * OUT_H;
    const int tx = threadIdx.x;
    const int ty = threadIdx.y;

    // ---- Slot-structured halo loader: ONE store per element ----
    // Element c goes to: x-half of P[c] (half-index 2c) if (c&2)==0,
    // else y-half of P[c-2] (half-index 2c-3).
    {
        int gxs[5], offs[5];
        #pragma unroll
        for (int k = 0; k < 5; k++) {
            int c = tx + 16 * k;
            gxs[k] = refl255(bx + c - PAD);
            offs[k] = ((c & 2) == 0) ? (2 * c) : (2 * c - 3);
        }
        int gy0 = refl255(by + ty - PAD);
        int gy1 = refl255(by + ty + 16 - PAD);

        #pragma unroll
        for (int j = 0; j < 2; j++) {
            int r = ty + 16 * j;
            if (j == 1 && ty >= TILE_H - 16) break;  // r<20
            const float* rowsrc = src + (j == 0 ? gy0 : gy1) * IMG;
            __half* base = reinterpret_cast<__half*>(&P[r][0]);
            #pragma unroll
            for (int k = 0; k < 5; k++) {
                if (k == 4 && tx >= TILE_W - 64) break;  // c<68
                base[offs[k]] = __float2half_rn(rowsrc[gxs[k]]);
            }
        }
    }
    __syncthreads();

    // Read packed cols 0,1,4,5 (two LDS.64 per row), sort each once.
    __half2 col0[5], col1[5], col4[5], col5[5];
    #pragma unroll
    for (int r = 0; r < 5; r++) {
        const __half2* rowp = &P[ty + r][tx * PPT];
        uint2 qa = *reinterpret_cast<const uint2*>(rowp);
        uint2 qb = *reinterpret_cast<const uint2*>(rowp + 4);
        col0[r] = *reinterpret_cast<__half2*>(&qa.x);
        col1[r] = *reinterpret_cast<__half2*>(&qa.y);
        col4[r] = *reinterpret_cast<__half2*>(&qb.x);
        col5[r] = *reinterpret_cast<__half2*>(&qb.y);
    }
    sort5p(col0[0], col0[1], col0[2], col0[3], col0[4]);
    sort5p(col1[0], col1[1], col1[2], col1[3], col1[4]);
    sort5p(col4[0], col4[1], col4[2], col4[3], col4[4]);
    sort5p(col5[0], col5[1], col5[2], col5[3], col5[4]);

    // Candidate sets for the two pairs (pair 0: cols 0..4, pair 1: cols 1..5).
    // Slot layout for double-elided minmax8:
    //   w0<=w1 : row0 (2nd max, max); w2<=w3 : row1 (third-of-top3, mx).
    __half2 w[2][8], s[2][5];

    // ---- Row 0 (column minima): top-2 set of 5. ----
    {
        __half2 x1 = col1[0], x4 = col4[0];
        __half2 x2 = midcol(col0[0], col4[0]);   // sorted C2 rank 0
        __half2 x3 = midcol(col1[0], col5[0]);   // sorted C3 rank 0
        cas2(x1, x2); cas2(x3, x4);
        __half2 T1 = __hmax2(x2, x4);
        __half2 T2 = __hmax2(__hmin2(x2, x4), __hmax2(x1, x3));
        __half2 e0 = col0[0], e1 = col5[0];
        w[0][1] = __hmax2(T1, e0); w[0][0] = __hmax2(T2, __hmin2(T1, e0));
        w[1][1] = __hmax2(T1, e1); w[1][0] = __hmax2(T2, __hmin2(T1, e1));
    }
    // ---- Row 1: top-3 set of 5: {mx, max(y,e), max(mn,min(y,e))}. ----
    {
        __half2 x1 = col1[1], x4 = col4[1];
        __half2 x2 = midcol(col0[1], col4[1]);
        __half2 x3 = midcol(col1[1], col5[1]);
        cas2(x1, x2); cas2(x3, x4);
        __half2 y  = __hmax2(x1, x3);
        __half2 mx = __hmax2(x2, x4), mn = __hmin2(x2, x4);
        __half2 e0 = col0[1], e1 = col5[1];
        w[0][3] = mx; w[0][4] = __hmax2(y, e0); w[0][2] = __hmax2(mn, __hmin2(y, e0));
        w[1][3] = mx; w[1][4] = __hmax2(y, e1); w[1][2] = __hmax2(mn, __hmin2(y, e1));
    }
    // ---- Row 2 (column medians): middle-3 set of 5. ----
    {
        __half2 x1 = col1[2], x4 = col4[2];
        __half2 x2 = midcol(col0[2], col4[2]);
        __half2 x3 = midcol(col1[2], col5[2]);
        cas2(x1, x2); cas2(x3, x4); cas2(x1, x3); cas2(x2, x4);
        __half2 e0 = col0[2], e1 = col5[2];
        w[0][5] = x2; w[0][6] = x3; w[0][7] = __hmin2(__hmax2(x1, e0), x4);
        w[1][5] = x2; w[1][6] = x3; w[1][7] = __hmin2(__hmax2(x1, e1), x4);
    }
    // ---- Row 3: bottom-3 set of 5. ----
    {
        __half2 x1 = col1[3], x4 = col4[3];
        __half2 x2 = midcol(col0[3], col4[3]);
        __half2 x3 = midcol(col1[3], col5[3]);
        cas2(x1, x2); cas2(x3, x4);
        __half2 z = __hmin2(x2, x4);
        __half2 m = __hmin2(x1, x3), M = __hmax2(x1, x3);
        __half2 e0 = col0[3], e1 = col5[3];
        s[0][0] = m; s[0][1] = __hmin2(z, e0); s[0][2] = __hmin2(M, __hmax2(z, e0));
        s[1][0] = m; s[1][1] = __hmin2(z, e1); s[1][2] = __hmin2(M, __hmax2(z, e1));
    }
    // ---- Row 4 (column maxima): bottom-2 set of 5. ----
    {
        __half2 x1 = col1[4], x4 = col4[4];
        __half2 x2 = midcol(col0[4], col4[4]);
        __half2 x3 = midcol(col1[4], col5[4]);
        cas2(x1, x2); cas2(x3, x4);
        __half2 B1 = __hmin2(x1, x3);
        __half2 B2 = __hmin2(__hmax2(x1, x3), __hmin2(x2, x4));
        __half2 e0 = col0[4], e1 = col5[4];
        s[0][3] = __hmin2(B1, e0); s[0][4] = __hmin2(B2, __hmax2(B1, e0));
        s[1][3] = __hmin2(B1, e1); s[1][4] = __hmin2(B2, __hmax2(B1, e1));
    }

    // Forgetful selection: median = rank 7 (1-indexed) of the 13 candidates.
    __half2 res[2];
    #pragma unroll
    for (int g = 0; g < 2; g++) {
        __half2 w0 = w[g][0], w1 = w[g][1], w2 = w[g][2], w3 = w[g][3];
        __half2 w4 = w[g][4], w5 = w[g][5], w6 = w[g][6], w7 = w[g][7];

        // minmax8 (tree); (w0,w1) and (w2,w3) pre-ordered -> 8 CAS.
        cas2(w4, w5); cas2(w6, w7);
        cas2(w0, w2); cas2(w4, w6); cas2(w0, w4);   // w0 = min8
        cas2(w1, w3); cas2(w5, w7); cas2(w3, w7);   // w7 = max8
        w0 = s[g][0];
        // minmax7: survivors w1..w5.
        cas2(w0, w1); cas2(w2, w3); cas2(w4, w5);
        cas2(w0, w2); cas2(w4, w6); cas2(w0, w4);
        cas2(w1, w3); cas2(w5, w6); cas2(w3, w6);
        w0 = s[g][1];
        // minmax6: survivors w1..w4.
        cas2(w0, w1); cas2(w2, w3); cas2(w4, w5);
        cas2(w0, w2); cas2(w0, w4);
        cas2(w1, w3); cas2(w3, w5);
        w0 = s[g][2];
        // minmax5: survivors w1, w2, w4.
        cas2(w0, w1); cas2(w2, w3); cas2(w0, w2); cas2(w1, w3); cas2(w0, w4); cas2(w4, w3);
        w0 = s[g][3];
        // minmax4 on (w0, w1, w2, w4): survivors w1, w2.
        cas2(w0, w1); cas2(w2, w4); cas2(w0, w2); cas2(w1, w4);
        // med3(s4, w1, w2) via 4-op identity.
        __half2 a = s[g][4];
        res[g] = __hmax2(__hmin2(a, w1), __hmin2(__hmax2(a, w1), w2));
    }

    // Unpack: pair0 = pixels (0,2), pair1 = pixels (1,3).
    float2 p0 = __half22float2(res[0]);
    float2 p1 = __half22float2(res[1]);
    float4 r4 = make_float4(p0.x, p1.x, p0.y, p1.y);

    const int gy = by + ty;
    *reinterpret_cast<float4*>(&dst[gy * IMG + bx + tx * PPT]) = r4;
}

extern "C" void kernel_launch(void* const* d_in, const int* in_sizes, int n_in,
                              void* d_out, int out_size) {
    const float* image = (const float*)d_in[0];
    float* out = (float*)d_out;
    (void)in_sizes; (void)n_in; (void)out_size;

    dim3 block(BX, BY);
    dim3 grid(IMG / OUT_W, IMG / OUT_H, 16 * 3);
    median5_kernel<<<grid, block>>>(image, out);
}